// round 6
// baseline (speedup 1.0000x reference)
#include <cuda_runtime.h>

// y = min(((x + 1) * 0.75)^2, 10)  — elementwise over 8192*8192 fp32.
// HBM-bound stream at the sustained roofline. Persistent grid: 2 CTAs/SM
// (296 blocks x 512 thr = single wave, full 32-warp occupancy), grid-stride
// loop of MLP-4 float4 batches (the proven R2 saturation point). Eliminates
// all wave transitions / block dispatch overhead.

#define T 512u
#define NBLK 296u   // 148 SMs * 2 CTAs

__device__ __forceinline__ float f(float x) {
    float t = (x + 1.0f) * 0.75f;
    float y = t * t;
    return fminf(y, 10.0f);
}

__device__ __forceinline__ float4 f4(float4 v) {
    float4 r;
    r.x = f(v.x); r.y = f(v.y); r.z = f(v.z); r.w = f(v.w);
    return r;
}

__global__ __launch_bounds__(512) void elemwise_kernel(const float4* __restrict__ in,
                                                       float4* __restrict__ out,
                                                       unsigned n4) {
    // Each grid pass covers NBLK*T*4 float4s; batches of 4 per thread (MLP=4).
    const unsigned stride = NBLK * T * 4u;                    // 606208
    unsigned base = blockIdx.x * (T * 4u) + threadIdx.x;

    // Full batches: all 4 loads in-bounds (uniform branch across warp since
    // n4 % T == 0 and offsets are multiples of T).
    for (; base + 3u * T < n4; base += stride) {
        float4 v0 = in[base + 0u * T];
        float4 v1 = in[base + 1u * T];
        float4 v2 = in[base + 2u * T];
        float4 v3 = in[base + 3u * T];
        out[base + 0u * T] = f4(v0);
        out[base + 1u * T] = f4(v1);
        out[base + 2u * T] = f4(v2);
        out[base + 3u * T] = f4(v3);
    }
    // Tail: remaining vectors one at a time.
    for (; base < n4; base += T) {
        out[base] = f4(in[base]);
    }
}

extern "C" void kernel_launch(void* const* d_in, const int* in_sizes, int n_in,
                              void* d_out, int out_size) {
    const float4* in = (const float4*)d_in[0];
    float4* out = (float4*)d_out;
    unsigned n = (unsigned)in_sizes[0];  // 67108864
    unsigned n4 = n / 4u;                // 16777216 float4s
    elemwise_kernel<<<NBLK, T>>>(in, out, n4);
}

// round 7
// speedup vs baseline: 1.0933x; 1.0933x over previous
#include <cuda_runtime.h>

// y = min(((x + 1) * 0.75)^2, 10)  — elementwise over 8192*8192 fp32.
// Final kernel = R2 structure (measured best: ncu 73.9us, DRAM 82.2%, wall 82.05us).
// HBM-bound at the sustained roofline: 4 independent front-batched float4 loads
// per thread (MLP_p1=4 — measured saturation point), default cache ops,
// coalesced at blockDim stride, many small blocks for HW load balancing.
// 67108864 elems = 16384 blocks * 256 thr * 16 elems (exact, no bounds checks).

#define VPT 4  // float4 vectors per thread

__device__ __forceinline__ float f(float x) {
    float t = (x + 1.0f) * 0.75f;
    float y = t * t;
    return fminf(y, 10.0f);
}

__device__ __forceinline__ float4 f4(float4 v) {
    float4 r;
    r.x = f(v.x); r.y = f(v.y); r.z = f(v.z); r.w = f(v.w);
    return r;
}

__global__ __launch_bounds__(256) void elemwise_kernel(const float4* __restrict__ in,
                                                       float4* __restrict__ out) {
    unsigned base = blockIdx.x * (blockDim.x * VPT) + threadIdx.x;

    // Front-batch all loads (independent -> MLP=4), then compute+store.
    float4 v0 = in[base + 0u * 256u];
    float4 v1 = in[base + 1u * 256u];
    float4 v2 = in[base + 2u * 256u];
    float4 v3 = in[base + 3u * 256u];

    out[base + 0u * 256u] = f4(v0);
    out[base + 1u * 256u] = f4(v1);
    out[base + 2u * 256u] = f4(v2);
    out[base + 3u * 256u] = f4(v3);
}

extern "C" void kernel_launch(void* const* d_in, const int* in_sizes, int n_in,
                              void* d_out, int out_size) {
    const float4* in = (const float4*)d_in[0];
    float4* out = (float4*)d_out;
    int n = in_sizes[0];                 // 67108864
    int n4 = n / 4;                      // 16777216 float4s
    int threads = 256;
    int blocks = n4 / (threads * VPT);   // 16384, exact
    elemwise_kernel<<<blocks, threads>>>(in, out);
}